// round 3
// baseline (speedup 1.0000x reference)
#include <cuda_runtime.h>

// Problem constants
#define BATCH 8
#define NUM   128
#define CH    512          // = H * D_K
#define HEADS 8
#define DK    64
#define NPOS  (BATCH*NUM*NUM)   // 131072 positions (b, i, j)
#define EPSV  1e-8f

// Global column mask (set of columns appearing in any top-4). No alloc allowed,
// so it lives in device global memory.
__device__ float g_colmask[NUM];

// ---------------------------------------------------------------------------
// Kernel 1: cosine-similarity attention.
// One warp per position (b,i,j); 8 warps (256 threads) per block.
// Lane l owns a quarter of head h = l>>2: floats [16l .. 16l+15] of the
// 512-float channel vector. 4 LDG.128 for q + 4 for k (MLP=8), 48 FFMA,
// then a 4-lane xor-shuffle reduction (2 levels x 3 vars = 6 SHFL).
// Lane with (l&3)==0 writes relu(dot / max(sqrt(qq*kk), eps)).
// Block 0 additionally zeroes g_colmask (stream-ordered before kernel 2).
// ---------------------------------------------------------------------------
__global__ __launch_bounds__(256) void attn_kernel(
    const float* __restrict__ q,
    const float* __restrict__ k,
    float* __restrict__ out)
{
    const int tidx = threadIdx.x;           // 0..255
    const int warp = tidx >> 5;             // 0..7 : position within block
    const int lane = tidx & 31;
    const int pos  = blockIdx.x * 8 + warp;

    if (blockIdx.x == 0 && tidx < NUM) g_colmask[tidx] = 0.0f;

    const float4* q4 = reinterpret_cast<const float4*>(q + (size_t)pos * CH);
    const float4* k4 = reinterpret_cast<const float4*>(k + (size_t)pos * CH);

    // Front-batched loads: 8 independent LDG.128
    float4 a0 = q4[4 * lane + 0];
    float4 a1 = q4[4 * lane + 1];
    float4 a2 = q4[4 * lane + 2];
    float4 a3 = q4[4 * lane + 3];
    float4 b0 = k4[4 * lane + 0];
    float4 b1 = k4[4 * lane + 1];
    float4 b2 = k4[4 * lane + 2];
    float4 b3 = k4[4 * lane + 3];

    float dot, qq, kk;
    dot  = a0.x*b0.x + a0.y*b0.y + a0.z*b0.z + a0.w*b0.w;
    dot += a1.x*b1.x + a1.y*b1.y + a1.z*b1.z + a1.w*b1.w;
    dot += a2.x*b2.x + a2.y*b2.y + a2.z*b2.z + a2.w*b2.w;
    dot += a3.x*b3.x + a3.y*b3.y + a3.z*b3.z + a3.w*b3.w;
    qq   = a0.x*a0.x + a0.y*a0.y + a0.z*a0.z + a0.w*a0.w;
    qq  += a1.x*a1.x + a1.y*a1.y + a1.z*a1.z + a1.w*a1.w;
    qq  += a2.x*a2.x + a2.y*a2.y + a2.z*a2.z + a2.w*a2.w;
    qq  += a3.x*a3.x + a3.y*a3.y + a3.z*a3.z + a3.w*a3.w;
    kk   = b0.x*b0.x + b0.y*b0.y + b0.z*b0.z + b0.w*b0.w;
    kk  += b1.x*b1.x + b1.y*b1.y + b1.z*b1.z + b1.w*b1.w;
    kk  += b2.x*b2.x + b2.y*b2.y + b2.z*b2.z + b2.w*b2.w;
    kk  += b3.x*b3.x + b3.y*b3.y + b3.z*b3.z + b3.w*b3.w;

    // Reduce across the 4 lanes of one head.
    #pragma unroll
    for (int m = 1; m <= 2; m <<= 1) {
        dot += __shfl_xor_sync(0xffffffffu, dot, m);
        qq  += __shfl_xor_sync(0xffffffffu, qq,  m);
        kk  += __shfl_xor_sync(0xffffffffu, kk,  m);
    }

    if ((lane & 3) == 0) {
        int h = lane >> 2;
        float denom = fmaxf(sqrtf(qq * kk), EPSV);
        float s = dot / denom;
        out[(size_t)pos * HEADS + h] = fmaxf(s, 0.0f);
    }
}

// ---------------------------------------------------------------------------
// Kernel 2: per-(b,i,h) top-4 over j (128 candidates), OR the winning column
// indices into g_colmask. One block per (b,i): 256 threads, 8 warps = 8 heads.
// Tile staged to smem transposed [h][j] with row pad 132 (conflict-free).
// Warp argmax with lowest-index tiebreak (matches lax.top_k ordering).
// ---------------------------------------------------------------------------
__global__ __launch_bounds__(256) void topk_kernel(const float* __restrict__ attn)
{
    __shared__ float sm[HEADS * 132];

    const int bi   = blockIdx.x;                  // (b*NUM + i), 0..1023
    const int tidx = threadIdx.x;                 // 0..255
    const float* row = attn + (size_t)bi * NUM * HEADS;  // 128 j x 8 h

    // Load 1024 floats, transpose into sm[h*132 + j]
    #pragma unroll
    for (int r = 0; r < 4; ++r) {
        int idx = tidx + r * 256;                 // idx = j*8 + h
        int h = idx & 7;
        int j = idx >> 3;
        sm[h * 132 + j] = row[idx];
    }
    __syncthreads();

    const int warp = tidx >> 5;                   // head
    const int lane = tidx & 31;

    float vals[4];
    #pragma unroll
    for (int m = 0; m < 4; ++m)
        vals[m] = sm[warp * 132 + lane + 32 * m];

    bool used[4] = {false, false, false, false};

    #pragma unroll
    for (int it = 0; it < 4; ++it) {
        float bv = -3.402823466e+38f;
        int   bj = 1 << 30;
        #pragma unroll
        for (int m = 0; m < 4; ++m) {
            int j = lane + 32 * m;
            if (!used[m] && (vals[m] > bv || (vals[m] == bv && j < bj))) {
                bv = vals[m];
                bj = j;
            }
        }
        // Warp argmax, min-index tiebreak — butterfly converges identically on
        // all lanes.
        #pragma unroll
        for (int m = 16; m; m >>= 1) {
            float ov = __shfl_xor_sync(0xffffffffu, bv, m);
            int   oj = __shfl_xor_sync(0xffffffffu, bj, m);
            if (ov > bv || (ov == bv && oj < bj)) { bv = ov; bj = oj; }
        }
        // Mark winner consumed on its owner lane.
        #pragma unroll
        for (int m = 0; m < 4; ++m)
            if (lane + 32 * m == bj) used[m] = true;

        if (lane == 0) g_colmask[bj] = 1.0f;       // benign race: same value
    }
}

// ---------------------------------------------------------------------------
// Kernel 3: out[b,i,j,:] *= roi[b,i,j] * colmask[j]. One thread per position,
// two float4 read-modify-writes (32B contiguous per thread).
// ---------------------------------------------------------------------------
__global__ __launch_bounds__(256) void apply_kernel(
    float* __restrict__ out,
    const float* __restrict__ roi)
{
    const int p = blockIdx.x * blockDim.x + threadIdx.x;   // 0..NPOS-1
    const int j = p & (NUM - 1);
    const float scale = roi[p] * g_colmask[j];

    float4* o = reinterpret_cast<float4*>(out + (size_t)p * HEADS);
    float4 x0 = o[0];
    float4 x1 = o[1];
    x0.x *= scale; x0.y *= scale; x0.z *= scale; x0.w *= scale;
    x1.x *= scale; x1.y *= scale; x1.z *= scale; x1.w *= scale;
    o[0] = x0;
    o[1] = x1;
}

// ---------------------------------------------------------------------------
extern "C" void kernel_launch(void* const* d_in, const int* in_sizes, int n_in,
                              void* d_out, int out_size)
{
    const float* q   = (const float*)d_in[0];
    const float* k   = (const float*)d_in[1];
    const float* roi = (const float*)d_in[2];
    float* out = (float*)d_out;

    // Kernel 1: attention + colmask zeroing. 8 positions per 256-thread block.
    attn_kernel<<<NPOS / 8, 256>>>(q, k, out);

    // Kernel 2: top-4 per (b,i,h) -> colmask. One block per (b,i).
    topk_kernel<<<BATCH * NUM, 256>>>(out);

    // Kernel 3: apply roi * colmask. One thread per (b,i,j).
    apply_kernel<<<NPOS / 256, 256>>>(out, roi);
}

// round 6
// speedup vs baseline: 1.2956x; 1.2956x over previous
#include <cuda_runtime.h>

// Problem constants
#define BATCH 8
#define NUM   128
#define CH    512          // = H * D_K
#define HEADS 8
#define DK    64
#define NPOS  (BATCH*NUM*NUM)   // 131072 positions (b, i, j)
#define NROWS (BATCH*NUM)       // 1024 (b, i) rows
#define EPSV  1e-8f

// Global column mask + arrival counter (no allocs allowed -> device globals).
__device__ float g_colmask[NUM];
__device__ int   g_counter;

// ---------------------------------------------------------------------------
// Kernel 1: cosine-similarity attention.
// 256 threads/block, 4 positions/block. Thread (tid) with t = tid&127 handles
// float4 column t of positions posA = blk*4 + (tid>>7) and posB = posA + 2.
// All loads warp-contiguous (4 wavefronts / 512B), 4-deep MLP, __ldcs
// streaming hint. 16-lane xor reduction per position; lane t%16==0 writes
// relu(dot / max(sqrt(qq*kk), eps)).
// Block 0 also zeroes g_colmask and g_counter (stream-ordered before k2).
// ---------------------------------------------------------------------------
__global__ __launch_bounds__(256) void attn_kernel(
    const float* __restrict__ q,
    const float* __restrict__ k,
    float* __restrict__ out)
{
    const int tidx = threadIdx.x;           // 0..255
    const int t    = tidx & 127;            // float4 column within position
    const int posA = blockIdx.x * 4 + (tidx >> 7);
    const int posB = posA + 2;

    if (blockIdx.x == 0) {
        if (tidx < NUM) g_colmask[tidx] = 0.0f;
        if (tidx == 0)  g_counter = 0;
    }

    const float4* qA = reinterpret_cast<const float4*>(q + (size_t)posA * CH);
    const float4* kA = reinterpret_cast<const float4*>(k + (size_t)posA * CH);
    const float4* qB = reinterpret_cast<const float4*>(q + (size_t)posB * CH);
    const float4* kB = reinterpret_cast<const float4*>(k + (size_t)posB * CH);

    // Front-batched, fully coalesced, streaming loads (MLP = 4).
    float4 a0 = __ldcs(qA + t);
    float4 b0 = __ldcs(kA + t);
    float4 a1 = __ldcs(qB + t);
    float4 b1 = __ldcs(kB + t);

    float dot0 = a0.x*b0.x + a0.y*b0.y + a0.z*b0.z + a0.w*b0.w;
    float qq0  = a0.x*a0.x + a0.y*a0.y + a0.z*a0.z + a0.w*a0.w;
    float kk0  = b0.x*b0.x + b0.y*b0.y + b0.z*b0.z + b0.w*b0.w;
    float dot1 = a1.x*b1.x + a1.y*b1.y + a1.z*b1.z + a1.w*b1.w;
    float qq1  = a1.x*a1.x + a1.y*a1.y + a1.z*a1.z + a1.w*a1.w;
    float kk1  = b1.x*b1.x + b1.y*b1.y + b1.z*b1.z + b1.w*b1.w;

    // Reduce across the 16 lanes of one head (both positions interleaved).
    #pragma unroll
    for (int m = 8; m; m >>= 1) {
        dot0 += __shfl_xor_sync(0xffffffffu, dot0, m);
        qq0  += __shfl_xor_sync(0xffffffffu, qq0,  m);
        kk0  += __shfl_xor_sync(0xffffffffu, kk0,  m);
        dot1 += __shfl_xor_sync(0xffffffffu, dot1, m);
        qq1  += __shfl_xor_sync(0xffffffffu, qq1,  m);
        kk1  += __shfl_xor_sync(0xffffffffu, kk1,  m);
    }

    if ((t & 15) == 0) {
        int h = t >> 4;
        float s0 = dot0 / fmaxf(sqrtf(qq0 * kk0), EPSV);
        float s1 = dot1 / fmaxf(sqrtf(qq1 * kk1), EPSV);
        out[(size_t)posA * HEADS + h] = fmaxf(s0, 0.0f);
        out[(size_t)posB * HEADS + h] = fmaxf(s1, 0.0f);
    }
}

// ---------------------------------------------------------------------------
// Kernel 2 (fused topk + apply): one block per (b,i) row, 1024 blocks.
// Phase A: per-(b,i,h) top-4 over j (warp per head), OR winners into
//          g_colmask. Tiebreak = lowest index (lax.top_k order).
// Barrier: counter-based grid barrier (1024 blocks <= single-wave capacity
//          1184 at 8 blocks/SM; __launch_bounds__(256,8) caps regs at 32).
// Phase B: out[row, j, :] *= roi[row, j] * colmask[j]; one float4 per thread.
// ---------------------------------------------------------------------------
__global__ __launch_bounds__(256, 8) void topk_apply_kernel(
    float* __restrict__ out,
    const float* __restrict__ roi)
{
    __shared__ float sm[HEADS * 132];

    const int bi   = blockIdx.x;                  // (b*NUM + i)
    const int tidx = threadIdx.x;                 // 0..255
    float* row = out + (size_t)bi * NUM * HEADS;  // 128 j x 8 h

    // ---- Phase A: load + transpose into sm[h*132 + j] ----
    #pragma unroll
    for (int r = 0; r < 4; ++r) {
        int idx = tidx + r * 256;                 // idx = j*8 + h
        sm[(idx & 7) * 132 + (idx >> 3)] = row[idx];
    }
    __syncthreads();

    const int warp = tidx >> 5;                   // head
    const int lane = tidx & 31;

    float vals[4];
    #pragma unroll
    for (int m = 0; m < 4; ++m)
        vals[m] = sm[warp * 132 + lane + 32 * m];

    bool used[4] = {false, false, false, false};

    #pragma unroll
    for (int it = 0; it < 4; ++it) {
        float bv = -3.402823466e+38f;
        int   bj = 1 << 30;
        #pragma unroll
        for (int m = 0; m < 4; ++m) {
            int j = lane + 32 * m;
            if (!used[m] && (vals[m] > bv || (vals[m] == bv && j < bj))) {
                bv = vals[m];
                bj = j;
            }
        }
        #pragma unroll
        for (int m = 16; m; m >>= 1) {
            float ov = __shfl_xor_sync(0xffffffffu, bv, m);
            int   oj = __shfl_xor_sync(0xffffffffu, bj, m);
            if (ov > bv || (ov == bv && oj < bj)) { bv = ov; bj = oj; }
        }
        #pragma unroll
        for (int m = 0; m < 4; ++m)
            if (lane + 32 * m == bj) used[m] = true;

        if (lane == 0) g_colmask[bj] = 1.0f;       // benign race: same value
    }

    // ---- Grid barrier: all 1024 blocks resident (single wave) ----
    __threadfence();
    __syncthreads();
    if (tidx == 0) {
        atomicAdd(&g_counter, 1);
        while (atomicAdd(&g_counter, 0) < NROWS) __nanosleep(64);
    }
    __syncthreads();
    __threadfence();

    // ---- Phase B: apply roi * colmask for this row ----
    // float4 chunk c = tidx covers j = c>>1, heads (c&1)*4 .. +3.
    const int j = tidx >> 1;
    const float scale = __ldcg(roi + bi * NUM + j) * __ldcg(&g_colmask[j]);

    float4* o4 = reinterpret_cast<float4*>(row);
    float4 x = o4[tidx];
    x.x *= scale; x.y *= scale; x.z *= scale; x.w *= scale;
    o4[tidx] = x;
}

// ---------------------------------------------------------------------------
extern "C" void kernel_launch(void* const* d_in, const int* in_sizes, int n_in,
                              void* d_out, int out_size)
{
    const float* q   = (const float*)d_in[0];
    const float* k   = (const float*)d_in[1];
    const float* roi = (const float*)d_in[2];
    float* out = (float*)d_out;

    attn_kernel<<<NPOS / 4, 256>>>(q, k, out);
    topk_apply_kernel<<<NROWS, 256>>>(out, roi);
}

// round 8
// speedup vs baseline: 1.3278x; 1.0249x over previous
#include <cuda_runtime.h>

// Problem constants
#define BATCH 8
#define NUM   128
#define CH    512          // = H * D_K
#define HEADS 8
#define DK    64
#define NPOS  (BATCH*NUM*NUM)   // 131072 positions (b, i, j)
#define NROWS (BATCH*NUM)       // 1024 (b, i) rows
#define EPSV  1e-8f

// Global column mask (no allocs allowed -> device global).
__device__ float g_colmask[NUM];

// ---------------------------------------------------------------------------
// Kernel 1: cosine-similarity attention.  (unchanged from R6 — measured
// ~73.7us @ ~7.0 TB/s)
// 256 threads/block, 4 positions/block. Thread tid with t = tid&127 handles
// float4 column t of positions posA = blk*4 + (tid>>7) and posB = posA + 2.
// All loads warp-contiguous (4 wavefronts / 512B), 4-deep MLP, __ldcs
// streaming hint. 16-lane xor reduction per position; lane t%16==0 writes
// relu(dot / max(sqrt(qq*kk), eps)).
// Block 0 also zeroes g_colmask (stream-ordered before kernel 2).
// ---------------------------------------------------------------------------
__global__ __launch_bounds__(256) void attn_kernel(
    const float* __restrict__ q,
    const float* __restrict__ k,
    float* __restrict__ out)
{
    const int tidx = threadIdx.x;           // 0..255
    const int t    = tidx & 127;            // float4 column within position
    const int posA = blockIdx.x * 4 + (tidx >> 7);
    const int posB = posA + 2;

    if (blockIdx.x == 0 && tidx < NUM) g_colmask[tidx] = 0.0f;

    const float4* qA = reinterpret_cast<const float4*>(q + (size_t)posA * CH);
    const float4* kA = reinterpret_cast<const float4*>(k + (size_t)posA * CH);
    const float4* qB = reinterpret_cast<const float4*>(q + (size_t)posB * CH);
    const float4* kB = reinterpret_cast<const float4*>(k + (size_t)posB * CH);

    // Front-batched, fully coalesced, streaming loads (MLP = 4).
    float4 a0 = __ldcs(qA + t);
    float4 b0 = __ldcs(kA + t);
    float4 a1 = __ldcs(qB + t);
    float4 b1 = __ldcs(kB + t);

    float dot0 = a0.x*b0.x + a0.y*b0.y + a0.z*b0.z + a0.w*b0.w;
    float qq0  = a0.x*a0.x + a0.y*a0.y + a0.z*a0.z + a0.w*a0.w;
    float kk0  = b0.x*b0.x + b0.y*b0.y + b0.z*b0.z + b0.w*b0.w;
    float dot1 = a1.x*b1.x + a1.y*b1.y + a1.z*b1.z + a1.w*b1.w;
    float qq1  = a1.x*a1.x + a1.y*a1.y + a1.z*a1.z + a1.w*a1.w;
    float kk1  = b1.x*b1.x + b1.y*b1.y + b1.z*b1.z + b1.w*b1.w;

    // Reduce across the 16 lanes of one head (both positions interleaved).
    #pragma unroll
    for (int m = 8; m; m >>= 1) {
        dot0 += __shfl_xor_sync(0xffffffffu, dot0, m);
        qq0  += __shfl_xor_sync(0xffffffffu, qq0,  m);
        kk0  += __shfl_xor_sync(0xffffffffu, kk0,  m);
        dot1 += __shfl_xor_sync(0xffffffffu, dot1, m);
        qq1  += __shfl_xor_sync(0xffffffffu, qq1,  m);
        kk1  += __shfl_xor_sync(0xffffffffu, kk1,  m);
    }

    if ((t & 15) == 0) {
        int h = t >> 4;
        float s0 = dot0 / fmaxf(sqrtf(qq0 * kk0), EPSV);
        float s1 = dot1 / fmaxf(sqrtf(qq1 * kk1), EPSV);
        out[(size_t)posA * HEADS + h] = fmaxf(s0, 0.0f);
        out[(size_t)posB * HEADS + h] = fmaxf(s1, 0.0f);
    }
}

// ---------------------------------------------------------------------------
// Kernel 2: per-(b,i,h) top-4 over j (128 candidates), OR the winning column
// indices into g_colmask. One block per (b,i): 256 threads, 8 warps = 8 heads.
// Tile staged to smem transposed [h][j] with row pad 132 (conflict-free).
// Warp argmax with lowest-index tiebreak (matches lax.top_k ordering).
// Data is L2-hot (attn_kernel just wrote it).
// ---------------------------------------------------------------------------
__global__ __launch_bounds__(256) void topk_kernel(const float* __restrict__ attn)
{
    __shared__ float sm[HEADS * 132];

    const int bi   = blockIdx.x;                  // (b*NUM + i), 0..1023
    const int tidx = threadIdx.x;                 // 0..255
    const float* row = attn + (size_t)bi * NUM * HEADS;  // 128 j x 8 h

    // Load 1024 floats, transpose into sm[h*132 + j]
    #pragma unroll
    for (int r = 0; r < 4; ++r) {
        int idx = tidx + r * 256;                 // idx = j*8 + h
        sm[(idx & 7) * 132 + (idx >> 3)] = __ldcg(row + idx);
    }
    __syncthreads();

    const int warp = tidx >> 5;                   // head
    const int lane = tidx & 31;

    float vals[4];
    #pragma unroll
    for (int m = 0; m < 4; ++m)
        vals[m] = sm[warp * 132 + lane + 32 * m];

    bool used[4] = {false, false, false, false};

    #pragma unroll
    for (int it = 0; it < 4; ++it) {
        float bv = -3.402823466e+38f;
        int   bj = 1 << 30;
        #pragma unroll
        for (int m = 0; m < 4; ++m) {
            int j = lane + 32 * m;
            if (!used[m] && (vals[m] > bv || (vals[m] == bv && j < bj))) {
                bv = vals[m];
                bj = j;
            }
        }
        // Warp argmax, min-index tiebreak — butterfly converges identically on
        // all lanes.
        #pragma unroll
        for (int m = 16; m; m >>= 1) {
            float ov = __shfl_xor_sync(0xffffffffu, bv, m);
            int   oj = __shfl_xor_sync(0xffffffffu, bj, m);
            if (ov > bv || (ov == bv && oj < bj)) { bv = ov; bj = oj; }
        }
        // Mark winner consumed on its owner lane.
        #pragma unroll
        for (int m = 0; m < 4; ++m)
            if (lane + 32 * m == bj) used[m] = true;

        if (lane == 0) g_colmask[bj] = 1.0f;       // benign race: same value
    }
}

// ---------------------------------------------------------------------------
// Kernel 3: out[b,i,j,:] *= roi[b,i,j] * colmask[j]. One thread per float4
// chunk (2 threads per position). L2-resident traffic.
// ---------------------------------------------------------------------------
__global__ __launch_bounds__(256) void apply_kernel(
    float* __restrict__ out,
    const float* __restrict__ roi)
{
    const int c = blockIdx.x * blockDim.x + threadIdx.x;  // 0..2*NPOS-1
    const int p = c >> 1;                                 // position
    const int j = p & (NUM - 1);
    const float scale = __ldg(roi + p) * g_colmask[j];

    float4* o = reinterpret_cast<float4*>(out) + c;
    float4 x = *o;
    x.x *= scale; x.y *= scale; x.z *= scale; x.w *= scale;
    *o = x;
}

// ---------------------------------------------------------------------------
extern "C" void kernel_launch(void* const* d_in, const int* in_sizes, int n_in,
                              void* d_out, int out_size)
{
    const float* q   = (const float*)d_in[0];
    const float* k   = (const float*)d_in[1];
    const float* roi = (const float*)d_in[2];
    float* out = (float*)d_out;

    attn_kernel<<<NPOS / 4, 256>>>(q, k, out);
    topk_kernel<<<NROWS, 256>>>(out);
    apply_kernel<<<NPOS * 2 / 256, 256>>>(out, roi);
}